// round 1
// baseline (speedup 1.0000x reference)
#include <cuda_runtime.h>
#include <math.h>

#define B 8
#define N 256
#define D 128
#define H 256
#define BN (B * N)   // 2048

// Scratch (allocation-free rule: device globals)
__device__ float g_hi[BN * H];   // slots @ W_m1[:D]
__device__ float g_hj[BN * H];   // slots @ W_m1[D:] + b_m1
__device__ float g_G [BN * H];   // sum_j a_ij * gelu(hi_i + hj_j)

__device__ __forceinline__ float gelu_exact(float x) {
    return 0.5f * x * (1.0f + erff(x * 0.70710678118654752440f));
}

// ---------------------------------------------------------------------------
// Kernel 1: hi/hjp projections. 16 rows per block, 256 threads (one per h).
// ---------------------------------------------------------------------------
__global__ __launch_bounds__(256) void proj_kernel(
    const float* __restrict__ slots, const float* __restrict__ W_m1,
    const float* __restrict__ b_m1)
{
    const int r0 = blockIdx.x * 16;     // global row = b*N + n
    const int h  = threadIdx.x;

    __shared__ float s_s[16][D];
    for (int idx = h; idx < 16 * D; idx += 256)
        ((float*)s_s)[idx] = slots[r0 * D + idx];
    __syncthreads();

    float acc_i[16], acc_j[16];
#pragma unroll
    for (int r = 0; r < 16; ++r) { acc_i[r] = 0.f; acc_j[r] = 0.f; }

    for (int d = 0; d < D; ++d) {
        const float wi = W_m1[d * H + h];
        const float wj = W_m1[(D + d) * H + h];
#pragma unroll
        for (int r = 0; r < 16; ++r) {
            const float sv = s_s[r][d];
            acc_i[r] = fmaf(sv, wi, acc_i[r]);
            acc_j[r] = fmaf(sv, wj, acc_j[r]);
        }
    }

    const float bm = b_m1[h];
#pragma unroll
    for (int r = 0; r < 16; ++r) {
        g_hi[(r0 + r) * H + h] = acc_i[r];
        g_hj[(r0 + r) * H + h] = acc_j[r] + bm;
    }
}

// ---------------------------------------------------------------------------
// Kernel 2 (dominant): G[b,i,h] = sum_j a[b,i,j] * gelu(hi[b,i,h] + hjp[b,j,h])
// 2 i-rows per block, 256 threads (one per h).
// ---------------------------------------------------------------------------
__global__ __launch_bounds__(256) void msg_agg_kernel(
    const float* __restrict__ adj)
{
    const int row0 = blockIdx.x * 2;        // global row = b*N + i
    const int b    = row0 >> 8;
    const int i0   = row0 & (N - 1);
    const int h    = threadIdx.x;

    __shared__ float a_s[2][N];
    const float* adj_b = adj + (size_t)b * N * N;
    a_s[0][h] = adj_b[ i0      * N + h];
    a_s[1][h] = adj_b[(i0 + 1) * N + h];
    __syncthreads();

    const float hi0 = g_hi[ row0      * H + h];
    const float hi1 = g_hi[(row0 + 1) * H + h];
    const float* hjb = g_hj + (size_t)b * N * H + h;

    float acc0 = 0.f, acc1 = 0.f;
#pragma unroll 4
    for (int j = 0; j < N; ++j) {
        const float hjv = hjb[j * H];
        acc0 = fmaf(a_s[0][j], gelu_exact(hi0 + hjv), acc0);
        acc1 = fmaf(a_s[1][j], gelu_exact(hi1 + hjv), acc1);
    }
    g_G[ row0      * H + h] = acc0;
    g_G[(row0 + 1) * H + h] = acc1;
}

// ---------------------------------------------------------------------------
// Kernel 3: fused epilogue. 16 rows per block, 256 threads.
//   agg = G @ W_m2 + rowsum(a)*b_m2
//   u   = slots@W_u1[:D] + agg@W_u1[D:] + b_u1 ; LayerNorm ; gelu
//   out = slots + u @ W_u2 + b_u2
// ---------------------------------------------------------------------------
__global__ __launch_bounds__(256) void epilogue_kernel(
    const float* __restrict__ slots, const float* __restrict__ adj,
    const float* __restrict__ W_m2, const float* __restrict__ b_m2,
    const float* __restrict__ W_u1, const float* __restrict__ b_u1,
    const float* __restrict__ ln_g, const float* __restrict__ ln_b,
    const float* __restrict__ W_u2, const float* __restrict__ b_u2,
    float* __restrict__ out)
{
    const int R  = 16;
    const int r0 = blockIdx.x * R;          // global row = b*N + n
    const int b  = r0 >> 8;
    const int n0 = r0 & (N - 1);
    const int tid = threadIdx.x;

    __shared__ float buf_s[R][H];           // G tile, later reused as u tile
    __shared__ float s_s [R][D];            // slots tile
    __shared__ float agg_s[R][D];
    __shared__ float red_s[R][16];
    __shared__ float asum_s[R];
    __shared__ float mu_s[R], rstd_s[R];

    // load G tile + slots tile
    for (int idx = tid; idx < R * H; idx += 256)
        ((float*)buf_s)[idx] = g_G[r0 * H + idx];
    for (int idx = tid; idx < R * D; idx += 256)
        ((float*)s_s)[idx] = slots[r0 * D + idx];

    // adjacency row sums (for b_m2 term)
    {
        const int r = tid >> 4, c = tid & 15;
        const float* arow = adj + ((size_t)b * N + n0 + r) * N + c * 16;
        float s = 0.f;
#pragma unroll
        for (int k = 0; k < 16; ++k) s += arow[k];
        red_s[r][c] = s;
    }
    __syncthreads();
    if (tid < R) {
        float s = 0.f;
#pragma unroll
        for (int c = 0; c < 16; ++c) s += red_s[tid][c];
        asum_s[tid] = s;
    }
    __syncthreads();

    // aggregated = G @ W_m2 + asum * b_m2
    {
        const int d  = tid & (D - 1);
        const int rb = (tid >> 7) * 8;      // rows rb..rb+7
        float acc[8];
        const float bm2 = b_m2[d];
#pragma unroll
        for (int r = 0; r < 8; ++r) acc[r] = asum_s[rb + r] * bm2;
        for (int hh = 0; hh < H; ++hh) {
            const float w = W_m2[hh * D + d];
#pragma unroll
            for (int r = 0; r < 8; ++r)
                acc[r] = fmaf(buf_s[rb + r][hh], w, acc[r]);
        }
#pragma unroll
        for (int r = 0; r < 8; ++r) agg_s[rb + r][d] = acc[r];
    }
    __syncthreads();

    // u = slots@W_u1[:D] + agg@W_u1[D:] + b_u1   (overwrite buf_s)
    {
        const int h = tid;
        float acc[R];
        const float bu = b_u1[h];
#pragma unroll
        for (int r = 0; r < R; ++r) acc[r] = bu;
        for (int d = 0; d < D; ++d) {
            const float w1 = W_u1[d * H + h];
            const float w2 = W_u1[(D + d) * H + h];
#pragma unroll
            for (int r = 0; r < R; ++r) {
                acc[r] = fmaf(s_s[r][d], w1, acc[r]);
                acc[r] = fmaf(agg_s[r][d], w2, acc[r]);
            }
        }
        __syncthreads();   // everyone done reading buf_s as G
#pragma unroll
        for (int r = 0; r < R; ++r) buf_s[r][h] = acc[r];
    }
    __syncthreads();

    // LayerNorm stats: warp w handles rows 2w, 2w+1 (two-pass for stability)
    {
        const int w = tid >> 5, lane = tid & 31;
        for (int rr = 0; rr < 2; ++rr) {
            const int r = w * 2 + rr;
            float s = 0.f;
            for (int k = lane; k < H; k += 32) s += buf_s[r][k];
#pragma unroll
            for (int o = 16; o > 0; o >>= 1) s += __shfl_xor_sync(~0u, s, o);
            const float mu = s * (1.f / H);
            float ss = 0.f;
            for (int k = lane; k < H; k += 32) {
                const float v = buf_s[r][k] - mu;
                ss += v * v;
            }
#pragma unroll
            for (int o = 16; o > 0; o >>= 1) ss += __shfl_xor_sync(~0u, ss, o);
            if (lane == 0) {
                mu_s[r]   = mu;
                rstd_s[r] = rsqrtf(ss * (1.f / H) + 1e-5f);
            }
        }
    }
    __syncthreads();

    // normalize + gelu (in place)
    {
        const int h = tid;
        const float g = ln_g[h], bb = ln_b[h];
#pragma unroll
        for (int r = 0; r < R; ++r) {
            const float v = (buf_s[r][h] - mu_s[r]) * rstd_s[r] * g + bb;
            buf_s[r][h] = gelu_exact(v);
        }
    }
    __syncthreads();

    // out = slots + u @ W_u2 + b_u2
    {
        const int d  = tid & (D - 1);
        const int rb = (tid >> 7) * 8;
        float acc[8];
        const float bu2 = b_u2[d];
#pragma unroll
        for (int r = 0; r < 8; ++r) acc[r] = bu2;
        for (int hh = 0; hh < H; ++hh) {
            const float w = W_u2[hh * D + d];
#pragma unroll
            for (int r = 0; r < 8; ++r)
                acc[r] = fmaf(buf_s[rb + r][hh], w, acc[r]);
        }
#pragma unroll
        for (int r = 0; r < 8; ++r)
            out[(r0 + rb + r) * D + d] = s_s[rb + r][d] + acc[r];
    }
}

// ---------------------------------------------------------------------------
extern "C" void kernel_launch(void* const* d_in, const int* in_sizes, int n_in,
                              void* d_out, int out_size)
{
    const float* slots = (const float*)d_in[0];
    const float* adj   = (const float*)d_in[1];
    const float* W_m1  = (const float*)d_in[2];
    const float* b_m1  = (const float*)d_in[3];
    const float* W_m2  = (const float*)d_in[4];
    const float* b_m2  = (const float*)d_in[5];
    const float* W_u1  = (const float*)d_in[6];
    const float* b_u1  = (const float*)d_in[7];
    const float* ln_g  = (const float*)d_in[8];
    const float* ln_b  = (const float*)d_in[9];
    const float* W_u2  = (const float*)d_in[10];
    const float* b_u2  = (const float*)d_in[11];
    float* out = (float*)d_out;

    proj_kernel<<<BN / 16, 256>>>(slots, W_m1, b_m1);
    msg_agg_kernel<<<BN / 2, 256>>>(adj);
    epilogue_kernel<<<BN / 16, 256>>>(slots, adj, W_m2, b_m2, W_u1, b_u1,
                                      ln_g, ln_b, W_u2, b_u2, out);
}

// round 2
// speedup vs baseline: 1.1421x; 1.1421x over previous
#include <cuda_runtime.h>
#include <math.h>

#define B 8
#define N 256
#define D 128
#define H 256
#define BN (B * N)   // 2048

typedef unsigned long long ull;

// Scratch (allocation-free rule: device globals), 16B aligned for f32x2/ull access
__device__ __align__(16) float g_hi[BN * H];   // slots @ W_m1[:D]
__device__ __align__(16) float g_hj[BN * H];   // slots @ W_m1[D:] + b_m1
__device__ __align__(16) float g_G [BN * H];   // sum_j a_ij * gelu(hi_i + hj_j)

__device__ __forceinline__ float gelu_exact(float x) {
    return 0.5f * x * (1.0f + erff(x * 0.70710678118654752440f));
}

__device__ __forceinline__ ull pack2(float f) {
    unsigned int u = __float_as_uint(f);
    return (ull)u * 0x100000001ULL;     // u | (u << 32)
}

#define F2ADD(d,a,b)   asm("add.rn.f32x2 %0,%1,%2;"    : "=l"(d) : "l"(a), "l"(b))
#define F2MUL(d,a,b)   asm("mul.rn.f32x2 %0,%1,%2;"    : "=l"(d) : "l"(a), "l"(b))
#define F2FMA(d,a,b,c) asm("fma.rn.f32x2 %0,%1,%2,%3;" : "=l"(d) : "l"(a), "l"(b), "l"(c))

// ---------------------------------------------------------------------------
// Kernel 1: hi/hjp projections. 8 rows per block, 256 threads (one per h).
// ---------------------------------------------------------------------------
__global__ __launch_bounds__(256) void proj_kernel(
    const float* __restrict__ slots, const float* __restrict__ W_m1,
    const float* __restrict__ b_m1)
{
    const int r0 = blockIdx.x * 8;      // global row = b*N + n
    const int h  = threadIdx.x;

    __shared__ float s_s[8][D];
    for (int idx = h; idx < 8 * D; idx += 256)
        ((float*)s_s)[idx] = slots[r0 * D + idx];
    __syncthreads();

    float acc_i[8], acc_j[8];
#pragma unroll
    for (int r = 0; r < 8; ++r) { acc_i[r] = 0.f; acc_j[r] = 0.f; }

#pragma unroll 4
    for (int d = 0; d < D; ++d) {
        const float wi = W_m1[d * H + h];
        const float wj = W_m1[(D + d) * H + h];
#pragma unroll
        for (int r = 0; r < 8; ++r) {
            const float sv = s_s[r][d];
            acc_i[r] = fmaf(sv, wi, acc_i[r]);
            acc_j[r] = fmaf(sv, wj, acc_j[r]);
        }
    }

    const float bm = b_m1[h];
#pragma unroll
    for (int r = 0; r < 8; ++r) {
        g_hi[(r0 + r) * H + h] = acc_i[r];
        g_hj[(r0 + r) * H + h] = acc_j[r] + bm;
    }
}

// ---------------------------------------------------------------------------
// Kernel 2 (dominant): G[b,i,h] = sum_j a[b,i,j] * gelu(hi[b,i,h] + hjp[b,j,h])
// 4 i-rows per block, 128 threads, each thread owns an h-pair (packed f32x2).
// gelu via branchless A&S 7.1.26 erf (max abs err 1.5e-7):
//   z = |x|/sqrt2; t = 1/(1+0.3275911 z); Y = P5(t) * exp(-z^2)
//   gelu(x) = 0.5*((x+|x|) - |x|*Y)
// ---------------------------------------------------------------------------
__global__ __launch_bounds__(128) void msg_agg_kernel(
    const float* __restrict__ adj)
{
    const int row0 = blockIdx.x * 4;        // global row = b*N + i
    const int b    = row0 >> 8;
    const int i0   = row0 & (N - 1);
    const int tid  = threadIdx.x;           // h-pair = (2*tid, 2*tid+1)

    __shared__ float a_s[4][N];             // prescaled by 0.5
    const float* adj_b = adj + ((size_t)b * N + i0) * N;
    for (int idx = tid; idx < 4 * N; idx += 128)
        ((float*)a_s)[idx] = 0.5f * adj_b[idx];
    __syncthreads();

    const ull ABSM = 0x7fffffff7fffffffULL;
    const ull SGNM = 0x8000000080000000ULL;
    const ull cis2  = pack2(0.70710678118654752440f);
    const ull cp    = pack2(0.3275911f);
    const ull cone  = pack2(1.0f);
    const ull ca1   = pack2(0.254829592f);
    const ull ca2   = pack2(-0.284496736f);
    const ull ca3   = pack2(1.421413741f);
    const ull ca4   = pack2(-1.453152027f);
    const ull ca5   = pack2(1.061405429f);
    const ull cnl2e = pack2(-1.4426950408889634f);

    const ull* hj2 = (const ull*)(g_hj + (size_t)b * N * H) + tid;
    ull hi2[4];
#pragma unroll
    for (int r = 0; r < 4; ++r)
        hi2[r] = ((const ull*)(g_hi + (size_t)(row0 + r) * H))[tid];

    ull acc[4] = {0ULL, 0ULL, 0ULL, 0ULL};  // packed {0.f,0.f}

#pragma unroll 4
    for (int j = 0; j < N; ++j) {
        const ull hjv = hj2[(size_t)j * (H / 2)];
#pragma unroll
        for (int r = 0; r < 4; ++r) {
            ull x; F2ADD(x, hi2[r], hjv);
            ull ax = x & ABSM;
            ull z;  F2MUL(z, ax, cis2);
            ull dd; F2FMA(dd, z, cp, cone);
            float dlo, dhi, tlo, thi;
            asm("mov.b64 {%0,%1},%2;" : "=f"(dlo), "=f"(dhi) : "l"(dd));
            asm("rcp.approx.f32 %0,%1;" : "=f"(tlo) : "f"(dlo));
            asm("rcp.approx.f32 %0,%1;" : "=f"(thi) : "f"(dhi));
            ull t; asm("mov.b64 %0,{%1,%2};" : "=l"(t) : "f"(tlo), "f"(thi));
            ull zz; F2MUL(zz, z, z);
            ull w;  F2MUL(w, zz, cnl2e);
            float wlo, whi, elo, ehi;
            asm("mov.b64 {%0,%1},%2;" : "=f"(wlo), "=f"(whi) : "l"(w));
            asm("ex2.approx.f32 %0,%1;" : "=f"(elo) : "f"(wlo));
            asm("ex2.approx.f32 %0,%1;" : "=f"(ehi) : "f"(whi));
            ull e; asm("mov.b64 %0,{%1,%2};" : "=l"(e) : "f"(elo), "f"(ehi));
            ull y;
            F2FMA(y, ca5, t, ca4);
            F2FMA(y, y, t, ca3);
            F2FMA(y, y, t, ca2);
            F2FMA(y, y, t, ca1);
            F2MUL(y, y, t);
            ull Y; F2MUL(Y, y, e);
            ull u; F2ADD(u, x, ax);
            ull nY = Y ^ SGNM;
            ull g2; F2FMA(g2, ax, nY, u);      // g2 = 2*gelu(x)
            const float av = a_s[r][j];        // = 0.5*a
            ull ap; asm("mov.b64 %0,{%1,%1};" : "=l"(ap) : "f"(av));
            F2FMA(acc[r], ap, g2, acc[r]);     // += a*gelu
        }
    }

#pragma unroll
    for (int r = 0; r < 4; ++r)
        ((ull*)(g_G + (size_t)(row0 + r) * H))[tid] = acc[r];
}

// ---------------------------------------------------------------------------
// Kernel 3: fused epilogue. 8 rows per block, 256 threads.
//   agg = G @ W_m2 + rowsum(a)*b_m2
//   u   = slots@W_u1[:D] + agg@W_u1[D:] + b_u1 ; LayerNorm ; gelu
//   out = slots + u @ W_u2 + b_u2
// ---------------------------------------------------------------------------
__global__ __launch_bounds__(256) void epilogue_kernel(
    const float* __restrict__ slots, const float* __restrict__ adj,
    const float* __restrict__ W_m2, const float* __restrict__ b_m2,
    const float* __restrict__ W_u1, const float* __restrict__ b_u1,
    const float* __restrict__ ln_g, const float* __restrict__ ln_b,
    const float* __restrict__ W_u2, const float* __restrict__ b_u2,
    float* __restrict__ out)
{
    const int R  = 8;
    const int r0 = blockIdx.x * R;          // global row = b*N + n
    const int b  = r0 >> 8;
    const int n0 = r0 & (N - 1);
    const int tid = threadIdx.x;
    const int warp = tid >> 5, lane = tid & 31;

    __shared__ float buf_s[R][H];           // G tile, later reused as u tile
    __shared__ float s_s [R][D];
    __shared__ float agg_s[R][D];
    __shared__ float asum_s[R];
    __shared__ float mu_s[R], rstd_s[R];

    for (int idx = tid; idx < R * H; idx += 256)
        ((float*)buf_s)[idx] = g_G[r0 * H + idx];
    for (int idx = tid; idx < R * D; idx += 256)
        ((float*)s_s)[idx] = slots[r0 * D + idx];

    // adjacency row sums: warp w handles row w
    {
        const float* arow = adj + ((size_t)b * N + n0 + warp) * N;
        float s = 0.f;
#pragma unroll
        for (int k = 0; k < 8; ++k) s += arow[lane + k * 32];
#pragma unroll
        for (int o = 16; o > 0; o >>= 1) s += __shfl_xor_sync(~0u, s, o);
        if (lane == 0) asum_s[warp] = s;
    }
    __syncthreads();

    // aggregated = G @ W_m2 + asum * b_m2
    {
        const int d  = tid & (D - 1);
        const int rb = (tid >> 7) * 4;       // rows rb..rb+3
        float acc[4];
        const float bm2 = b_m2[d];
#pragma unroll
        for (int r = 0; r < 4; ++r) acc[r] = asum_s[rb + r] * bm2;
#pragma unroll 4
        for (int hh = 0; hh < H; ++hh) {
            const float w = W_m2[hh * D + d];
#pragma unroll
            for (int r = 0; r < 4; ++r)
                acc[r] = fmaf(buf_s[rb + r][hh], w, acc[r]);
        }
        __syncthreads();                     // all reads of buf_s-as-G done
#pragma unroll
        for (int r = 0; r < 4; ++r) agg_s[rb + r][d] = acc[r];
    }
    __syncthreads();

    // u = slots@W_u1[:D] + agg@W_u1[D:] + b_u1   (overwrite buf_s)
    {
        const int h = tid;
        float acc[R];
        const float bu = b_u1[h];
#pragma unroll
        for (int r = 0; r < R; ++r) acc[r] = bu;
#pragma unroll 4
        for (int d = 0; d < D; ++d) {
            const float w1 = W_u1[d * H + h];
            const float w2 = W_u1[(D + d) * H + h];
#pragma unroll
            for (int r = 0; r < R; ++r) {
                acc[r] = fmaf(s_s[r][d], w1, acc[r]);
                acc[r] = fmaf(agg_s[r][d], w2, acc[r]);
            }
        }
#pragma unroll
        for (int r = 0; r < R; ++r) buf_s[r][h] = acc[r];
    }
    __syncthreads();

    // LayerNorm stats: warp w handles row w (two-pass)
    {
        const int r = warp;
        float s = 0.f;
#pragma unroll
        for (int k = 0; k < 8; ++k) s += buf_s[r][lane + k * 32];
#pragma unroll
        for (int o = 16; o > 0; o >>= 1) s += __shfl_xor_sync(~0u, s, o);
        const float mu = s * (1.f / H);
        float ss = 0.f;
#pragma unroll
        for (int k = 0; k < 8; ++k) {
            const float v = buf_s[r][lane + k * 32] - mu;
            ss += v * v;
        }
#pragma unroll
        for (int o = 16; o > 0; o >>= 1) ss += __shfl_xor_sync(~0u, ss, o);
        if (lane == 0) {
            mu_s[r]   = mu;
            rstd_s[r] = rsqrtf(ss * (1.f / H) + 1e-5f);
        }
    }
    __syncthreads();

    // normalize + gelu (in place)
    {
        const int h = tid;
        const float g = ln_g[h], bb = ln_b[h];
#pragma unroll
        for (int r = 0; r < R; ++r) {
            const float v = (buf_s[r][h] - mu_s[r]) * rstd_s[r] * g + bb;
            buf_s[r][h] = gelu_exact(v);
        }
    }
    __syncthreads();

    // out = slots + u @ W_u2 + b_u2
    {
        const int d  = tid & (D - 1);
        const int rb = (tid >> 7) * 4;
        float acc[4];
        const float bu2 = b_u2[d];
#pragma unroll
        for (int r = 0; r < 4; ++r) acc[r] = bu2;
#pragma unroll 4
        for (int hh = 0; hh < H; ++hh) {
            const float w = W_u2[hh * D + d];
#pragma unroll
            for (int r = 0; r < 4; ++r)
                acc[r] = fmaf(buf_s[rb + r][hh], w, acc[r]);
        }
#pragma unroll
        for (int r = 0; r < 4; ++r)
            out[(r0 + rb + r) * D + d] = s_s[rb + r][d] + acc[r];
    }
}

// ---------------------------------------------------------------------------
extern "C" void kernel_launch(void* const* d_in, const int* in_sizes, int n_in,
                              void* d_out, int out_size)
{
    const float* slots = (const float*)d_in[0];
    const float* adj   = (const float*)d_in[1];
    const float* W_m1  = (const float*)d_in[2];
    const float* b_m1  = (const float*)d_in[3];
    const float* W_m2  = (const float*)d_in[4];
    const float* b_m2  = (const float*)d_in[5];
    const float* W_u1  = (const float*)d_in[6];
    const float* b_u1  = (const float*)d_in[7];
    const float* ln_g  = (const float*)d_in[8];
    const float* ln_b  = (const float*)d_in[9];
    const float* W_u2  = (const float*)d_in[10];
    const float* b_u2  = (const float*)d_in[11];
    float* out = (float*)d_out;

    proj_kernel<<<BN / 8, 256>>>(slots, W_m1, b_m1);
    msg_agg_kernel<<<BN / 4, 128>>>(adj);
    epilogue_kernel<<<BN / 8, 256>>>(slots, adj, W_m2, b_m2, W_u1, b_u1,
                                     ln_g, ln_b, W_u2, b_u2, out);
}

// round 3
// speedup vs baseline: 1.3887x; 1.2159x over previous
#include <cuda_runtime.h>
#include <math.h>

#define B 8
#define N 256
#define D 128
#define H 256
#define BN (B * N)   // 2048

typedef unsigned long long ull;

// Scratch (allocation-free rule: device globals), 16B aligned for f32x2/ull access
__device__ __align__(16) float g_hi[BN * H];   // slots @ W_m1[:D]
__device__ __align__(16) float g_hj[BN * H];   // slots @ W_m1[D:] + b_m1
__device__ __align__(16) float g_G [BN * H];   // sum_j a_ij * gelu(hi_i + hj_j)

__device__ __forceinline__ float gelu_exact(float x) {
    return 0.5f * x * (1.0f + erff(x * 0.70710678118654752440f));
}

__device__ __forceinline__ ull pack2(float f) {
    unsigned int u = __float_as_uint(f);
    return (ull)u * 0x100000001ULL;     // u | (u << 32)
}

#define F2ADD(d,a,b)   asm("add.rn.f32x2 %0,%1,%2;"    : "=l"(d) : "l"(a), "l"(b))
#define F2MUL(d,a,b)   asm("mul.rn.f32x2 %0,%1,%2;"    : "=l"(d) : "l"(a), "l"(b))
#define F2FMA(d,a,b,c) asm("fma.rn.f32x2 %0,%1,%2,%3;" : "=l"(d) : "l"(a), "l"(b), "l"(c))

// ---------------------------------------------------------------------------
// Kernel 1: hi/hjp projections. 4 rows per block (grid 512), 256 threads.
// ---------------------------------------------------------------------------
__global__ __launch_bounds__(256) void proj_kernel(
    const float* __restrict__ slots, const float* __restrict__ W_m1,
    const float* __restrict__ b_m1)
{
    const int r0 = blockIdx.x * 4;      // global row = b*N + n
    const int h  = threadIdx.x;

    __shared__ float s_s[4][D];
    for (int idx = h; idx < 4 * D; idx += 256)
        ((float*)s_s)[idx] = slots[r0 * D + idx];
    __syncthreads();

    float acc_i[4], acc_j[4];
#pragma unroll
    for (int r = 0; r < 4; ++r) { acc_i[r] = 0.f; acc_j[r] = 0.f; }

#pragma unroll 8
    for (int d = 0; d < D; ++d) {
        const float wi = W_m1[d * H + h];
        const float wj = W_m1[(D + d) * H + h];
#pragma unroll
        for (int r = 0; r < 4; ++r) {
            const float sv = s_s[r][d];
            acc_i[r] = fmaf(sv, wi, acc_i[r]);
            acc_j[r] = fmaf(sv, wj, acc_j[r]);
        }
    }

    const float bm = b_m1[h];
#pragma unroll
    for (int r = 0; r < 4; ++r) {
        g_hi[(r0 + r) * H + h] = acc_i[r];
        g_hj[(r0 + r) * H + h] = acc_j[r] + bm;
    }
}

// ---------------------------------------------------------------------------
// Kernel 2 (dominant): G[b,i,h] = sum_j a[b,i,j] * gelu(hi[b,i,h] + hjp[b,j,h])
// 2 i-rows per block (grid 1024), 128 threads, each thread owns an h-pair.
// gelu via branchless A&S 7.1.26 erf (max abs err 1.5e-7):
//   z = |x|/sqrt2; t = 1/(1+0.3275911 z); Y = P5(t) * exp(-z^2)
//   gelu(x) = 0.5*((x+|x|) - |x|*Y)
// ---------------------------------------------------------------------------
__global__ __launch_bounds__(128) void msg_agg_kernel(
    const float* __restrict__ adj)
{
    const int row0 = blockIdx.x * 2;        // global row = b*N + i
    const int b    = row0 >> 8;
    const int i0   = row0 & (N - 1);
    const int tid  = threadIdx.x;           // h-pair = (2*tid, 2*tid+1)

    __shared__ float a_s[2][N];             // prescaled by 0.5
    const float* adj_b = adj + ((size_t)b * N + i0) * N;
#pragma unroll
    for (int idx = tid; idx < 2 * N; idx += 128)
        ((float*)a_s)[idx] = 0.5f * adj_b[idx];
    __syncthreads();

    const ull ABSM = 0x7fffffff7fffffffULL;
    const ull SGNM = 0x8000000080000000ULL;
    const ull cis2  = pack2(0.70710678118654752440f);
    const ull cp    = pack2(0.3275911f);
    const ull cone  = pack2(1.0f);
    const ull ca1   = pack2(0.254829592f);
    const ull ca2   = pack2(-0.284496736f);
    const ull ca3   = pack2(1.421413741f);
    const ull ca4   = pack2(-1.453152027f);
    const ull ca5   = pack2(1.061405429f);
    const ull cnl2e = pack2(-1.4426950408889634f);

    const ull* hj2 = (const ull*)(g_hj + (size_t)b * N * H) + tid;
    ull hi2[2];
    hi2[0] = ((const ull*)(g_hi + (size_t) row0      * H))[tid];
    hi2[1] = ((const ull*)(g_hi + (size_t)(row0 + 1) * H))[tid];

    ull acc[2] = {0ULL, 0ULL};              // packed {0.f,0.f}

#pragma unroll 8
    for (int j = 0; j < N; ++j) {
        const ull hjv = hj2[(size_t)j * (H / 2)];
#pragma unroll
        for (int r = 0; r < 2; ++r) {
            ull x; F2ADD(x, hi2[r], hjv);
            ull ax = x & ABSM;
            ull z;  F2MUL(z, ax, cis2);
            ull dd; F2FMA(dd, z, cp, cone);
            float dlo, dhi, tlo, thi;
            asm("mov.b64 {%0,%1},%2;" : "=f"(dlo), "=f"(dhi) : "l"(dd));
            asm("rcp.approx.f32 %0,%1;" : "=f"(tlo) : "f"(dlo));
            asm("rcp.approx.f32 %0,%1;" : "=f"(thi) : "f"(dhi));
            ull t; asm("mov.b64 %0,{%1,%2};" : "=l"(t) : "f"(tlo), "f"(thi));
            ull zz; F2MUL(zz, z, z);
            ull w;  F2MUL(w, zz, cnl2e);
            float wlo, whi, elo, ehi;
            asm("mov.b64 {%0,%1},%2;" : "=f"(wlo), "=f"(whi) : "l"(w));
            asm("ex2.approx.f32 %0,%1;" : "=f"(elo) : "f"(wlo));
            asm("ex2.approx.f32 %0,%1;" : "=f"(ehi) : "f"(whi));
            ull e; asm("mov.b64 %0,{%1,%2};" : "=l"(e) : "f"(elo), "f"(ehi));
            ull y;
            F2FMA(y, ca5, t, ca4);
            F2FMA(y, y, t, ca3);
            F2FMA(y, y, t, ca2);
            F2FMA(y, y, t, ca1);
            F2MUL(y, y, t);
            ull Y; F2MUL(Y, y, e);
            ull u; F2ADD(u, x, ax);
            ull nY = Y ^ SGNM;
            ull g2; F2FMA(g2, ax, nY, u);      // g2 = 2*gelu(x)
            const float av = a_s[r][j];        // = 0.5*a
            ull ap; asm("mov.b64 %0,{%1,%1};" : "=l"(ap) : "f"(av));
            F2FMA(acc[r], ap, g2, acc[r]);     // += a*gelu
        }
    }

    ((ull*)(g_G + (size_t) row0      * H))[tid] = acc[0];
    ((ull*)(g_G + (size_t)(row0 + 1) * H))[tid] = acc[1];
}

// ---------------------------------------------------------------------------
// Kernel 3: fused epilogue. 4 rows per block (grid 512), 256 threads.
//   agg = G @ W_m2 + rowsum(a)*b_m2
//   u   = slots@W_u1[:D] + agg@W_u1[D:] + b_u1 ; LayerNorm ; gelu
//   out = slots + u @ W_u2 + b_u2
// ---------------------------------------------------------------------------
__global__ __launch_bounds__(256) void epilogue_kernel(
    const float* __restrict__ slots, const float* __restrict__ adj,
    const float* __restrict__ W_m2, const float* __restrict__ b_m2,
    const float* __restrict__ W_u1, const float* __restrict__ b_u1,
    const float* __restrict__ ln_g, const float* __restrict__ ln_b,
    const float* __restrict__ W_u2, const float* __restrict__ b_u2,
    float* __restrict__ out)
{
    const int R  = 4;
    const int r0 = blockIdx.x * R;          // global row = b*N + n
    const int b  = r0 >> 8;
    const int n0 = r0 & (N - 1);
    const int tid = threadIdx.x;
    const int warp = tid >> 5, lane = tid & 31;

    __shared__ float buf_s[R][H];           // G tile, later reused as u tile
    __shared__ float s_s [R][D];
    __shared__ float agg_s[R][D];
    __shared__ float asum_s[R];
    __shared__ float mu_s[R], rstd_s[R];

    for (int idx = tid; idx < R * H; idx += 256)
        ((float*)buf_s)[idx] = g_G[r0 * H + idx];
    for (int idx = tid; idx < R * D; idx += 256)
        ((float*)s_s)[idx] = slots[r0 * D + idx];

    // adjacency row sums: warps 0..3 handle rows 0..3
    if (warp < R) {
        const float* arow = adj + ((size_t)b * N + n0 + warp) * N;
        float s = 0.f;
#pragma unroll
        for (int k = 0; k < 8; ++k) s += arow[lane + k * 32];
#pragma unroll
        for (int o = 16; o > 0; o >>= 1) s += __shfl_xor_sync(~0u, s, o);
        if (lane == 0) asum_s[warp] = s;
    }
    __syncthreads();

    // aggregated = G @ W_m2 + asum * b_m2
    {
        const int d  = tid & (D - 1);
        const int rb = (tid >> 7) * 2;       // rows rb, rb+1
        float acc[2];
        const float bm2 = b_m2[d];
#pragma unroll
        for (int r = 0; r < 2; ++r) acc[r] = asum_s[rb + r] * bm2;
#pragma unroll 8
        for (int hh = 0; hh < H; ++hh) {
            const float w = W_m2[hh * D + d];
#pragma unroll
            for (int r = 0; r < 2; ++r)
                acc[r] = fmaf(buf_s[rb + r][hh], w, acc[r]);
        }
        __syncthreads();                     // all reads of buf_s-as-G done
#pragma unroll
        for (int r = 0; r < 2; ++r) agg_s[rb + r][d] = acc[r];
    }
    __syncthreads();

    // u = slots@W_u1[:D] + agg@W_u1[D:] + b_u1   (overwrite buf_s)
    {
        const int h = tid;
        float acc[R];
        const float bu = b_u1[h];
#pragma unroll
        for (int r = 0; r < R; ++r) acc[r] = bu;
#pragma unroll 8
        for (int d = 0; d < D; ++d) {
            const float w1 = W_u1[d * H + h];
            const float w2 = W_u1[(D + d) * H + h];
#pragma unroll
            for (int r = 0; r < R; ++r) {
                acc[r] = fmaf(s_s[r][d], w1, acc[r]);
                acc[r] = fmaf(agg_s[r][d], w2, acc[r]);
            }
        }
#pragma unroll
        for (int r = 0; r < R; ++r) buf_s[r][h] = acc[r];
    }
    __syncthreads();

    // LayerNorm stats: warps 0..3, one row each (two-pass)
    if (warp < R) {
        const int r = warp;
        float s = 0.f;
#pragma unroll
        for (int k = 0; k < 8; ++k) s += buf_s[r][lane + k * 32];
#pragma unroll
        for (int o = 16; o > 0; o >>= 1) s += __shfl_xor_sync(~0u, s, o);
        const float mu = s * (1.f / H);
        float ss = 0.f;
#pragma unroll
        for (int k = 0; k < 8; ++k) {
            const float v = buf_s[r][lane + k * 32] - mu;
            ss += v * v;
        }
#pragma unroll
        for (int o = 16; o > 0; o >>= 1) ss += __shfl_xor_sync(~0u, ss, o);
        if (lane == 0) {
            mu_s[r]   = mu;
            rstd_s[r] = rsqrtf(ss * (1.f / H) + 1e-5f);
        }
    }
    __syncthreads();

    // normalize + gelu (in place)
    {
        const int h = tid;
        const float g = ln_g[h], bb = ln_b[h];
#pragma unroll
        for (int r = 0; r < R; ++r) {
            const float v = (buf_s[r][h] - mu_s[r]) * rstd_s[r] * g + bb;
            buf_s[r][h] = gelu_exact(v);
        }
    }
    __syncthreads();

    // out = slots + u @ W_u2 + b_u2
    {
        const int d  = tid & (D - 1);
        const int rb = (tid >> 7) * 2;
        float acc[2];
        const float bu2 = b_u2[d];
#pragma unroll
        for (int r = 0; r < 2; ++r) acc[r] = bu2;
#pragma unroll 8
        for (int hh = 0; hh < H; ++hh) {
            const float w = W_u2[hh * D + d];
#pragma unroll
            for (int r = 0; r < 2; ++r)
                acc[r] = fmaf(buf_s[rb + r][hh], w, acc[r]);
        }
#pragma unroll
        for (int r = 0; r < 2; ++r)
            out[(r0 + rb + r) * D + d] = s_s[rb + r][d] + acc[r];
    }
}

// ---------------------------------------------------------------------------
extern "C" void kernel_launch(void* const* d_in, const int* in_sizes, int n_in,
                              void* d_out, int out_size)
{
    const float* slots = (const float*)d_in[0];
    const float* adj   = (const float*)d_in[1];
    const float* W_m1  = (const float*)d_in[2];
    const float* b_m1  = (const float*)d_in[3];
    const float* W_m2  = (const float*)d_in[4];
    const float* b_m2  = (const float*)d_in[5];
    const float* W_u1  = (const float*)d_in[6];
    const float* b_u1  = (const float*)d_in[7];
    const float* ln_g  = (const float*)d_in[8];
    const float* ln_b  = (const float*)d_in[9];
    const float* W_u2  = (const float*)d_in[10];
    const float* b_u2  = (const float*)d_in[11];
    float* out = (float*)d_out;

    proj_kernel<<<BN / 4, 256>>>(slots, W_m1, b_m1);
    msg_agg_kernel<<<BN / 2, 128>>>(adj);
    epilogue_kernel<<<BN / 4, 256>>>(slots, adj, W_m2, b_m2, W_u1, b_u1,
                                     ln_g, ln_b, W_u2, b_u2, out);
}

// round 4
// speedup vs baseline: 1.4564x; 1.0487x over previous
#include <cuda_runtime.h>
#include <math.h>

#define B 8
#define N 256
#define D 128
#define H 256
#define BN (B * N)   // 2048

typedef unsigned long long ull;

// Scratch (allocation-free rule: device globals), 16B aligned for f32x2/ull access
__device__ __align__(16) float g_hi[BN * H];   // slots @ W_m1[:D]
__device__ __align__(16) float g_hj[BN * H];   // slots @ W_m1[D:] + b_m1
__device__ __align__(16) float g_G [BN * H];   // sum_j a_ij * gelu(hi_i + hj_j)

__device__ __forceinline__ float gelu_exact(float x) {
    return 0.5f * x * (1.0f + erff(x * 0.70710678118654752440f));
}

__device__ __forceinline__ ull pack2(float f) {
    unsigned int u = __float_as_uint(f);
    return (ull)u * 0x100000001ULL;     // u | (u << 32)
}

#define F2ADD(d,a,b)   asm("add.rn.f32x2 %0,%1,%2;"    : "=l"(d) : "l"(a), "l"(b))
#define F2MUL(d,a,b)   asm("mul.rn.f32x2 %0,%1,%2;"    : "=l"(d) : "l"(a), "l"(b))
#define F2FMA(d,a,b,c) asm("fma.rn.f32x2 %0,%1,%2,%3;" : "=l"(d) : "l"(a), "l"(b), "l"(c))

// ---------------------------------------------------------------------------
// Kernel 1: hi/hjp projections. 8 rows per block, 512 threads (grid 256).
// Thread-groups g=tid>>8 handle rows 4g..4g+3; both groups load the SAME
// weight addresses -> L1/MSHR dedup halves L2 weight traffic vs grid 512.
// ---------------------------------------------------------------------------
__global__ __launch_bounds__(512) void proj_kernel(
    const float* __restrict__ slots, const float* __restrict__ W_m1,
    const float* __restrict__ b_m1)
{
    const int r0  = blockIdx.x * 8;      // global row = b*N + n
    const int tid = threadIdx.x;
    const int h   = tid & 255;
    const int g   = tid >> 8;            // 0,1

    __shared__ float s_s[8][D];
    for (int idx = tid; idx < 8 * D; idx += 512)
        ((float*)s_s)[idx] = slots[r0 * D + idx];
    __syncthreads();

    float acc_i[4], acc_j[4];
#pragma unroll
    for (int r = 0; r < 4; ++r) { acc_i[r] = 0.f; acc_j[r] = 0.f; }

#pragma unroll 8
    for (int d = 0; d < D; ++d) {
        const float wi = W_m1[d * H + h];
        const float wj = W_m1[(D + d) * H + h];
#pragma unroll
        for (int r = 0; r < 4; ++r) {
            const float sv = s_s[4 * g + r][d];
            acc_i[r] = fmaf(sv, wi, acc_i[r]);
            acc_j[r] = fmaf(sv, wj, acc_j[r]);
        }
    }

    const float bm = b_m1[h];
#pragma unroll
    for (int r = 0; r < 4; ++r) {
        g_hi[(r0 + 4 * g + r) * H + h] = acc_i[r];
        g_hj[(r0 + 4 * g + r) * H + h] = acc_j[r] + bm;
    }
}

// ---------------------------------------------------------------------------
// Kernel 2 (dominant): G[b,i,h] = sum_j a[b,i,j] * gelu(hi[b,i,h] + hjp[b,j,h])
// 2 i-rows per block (grid 1024), 128 threads, each thread owns an h-pair.
// gelu via branchless A&S 7.1.28 (max abs err 3e-7):
//   z = |x|/sqrt2; P = 1 + b1 z + ... + b6 z^6; erf = 1 - P^-16
//   gelu(x) = 0.5*((x+|x|) - |x| * P^-16)
// One rcp per element, no exp, no pack/unpack except around rcp.
// ---------------------------------------------------------------------------
__global__ __launch_bounds__(128) void msg_agg_kernel(
    const float* __restrict__ adj)
{
    const int row0 = blockIdx.x * 2;        // global row = b*N + i
    const int b    = row0 >> 8;
    const int i0   = row0 & (N - 1);
    const int tid  = threadIdx.x;           // h-pair = (2*tid, 2*tid+1)

    __shared__ ull a2_s[2][N];              // packed {0.5a, 0.5a}
    const float* adj_b = adj + ((size_t)b * N + i0) * N;
#pragma unroll
    for (int idx = tid; idx < 2 * N; idx += 128) {
        const float av = 0.5f * adj_b[idx];
        ((ull*)a2_s)[idx] = pack2(av);
    }
    __syncthreads();

    const ull ABSM = 0x7fffffff7fffffffULL;
    const ull SGNM = 0x8000000080000000ULL;
    const ull cis2 = pack2(0.70710678118654752440f);
    const ull cone = pack2(1.0f);
    const ull cb1  = pack2(0.0705230784f);
    const ull cb2  = pack2(0.0422820123f);
    const ull cb3  = pack2(0.0092705272f);
    const ull cb4  = pack2(0.0001520143f);
    const ull cb5  = pack2(0.0002765672f);
    const ull cb6  = pack2(0.0000430638f);

    const ull* hj2 = (const ull*)(g_hj + (size_t)b * N * H) + tid;
    ull hi2[2];
    hi2[0] = ((const ull*)(g_hi + (size_t) row0      * H))[tid];
    hi2[1] = ((const ull*)(g_hi + (size_t)(row0 + 1) * H))[tid];

    ull acc[2] = {0ULL, 0ULL};              // packed {0.f,0.f}

#pragma unroll 8
    for (int j = 0; j < N; ++j) {
        const ull hjv = hj2[(size_t)j * (H / 2)];
#pragma unroll
        for (int r = 0; r < 2; ++r) {
            ull x; F2ADD(x, hi2[r], hjv);
            const ull ax = x & ABSM;
            ull z; F2MUL(z, ax, cis2);
            ull p;
            F2FMA(p, cb6, z, cb5);
            F2FMA(p, p, z, cb4);
            F2FMA(p, p, z, cb3);
            F2FMA(p, p, z, cb2);
            F2FMA(p, p, z, cb1);
            F2FMA(p, p, z, cone);           // P
            F2MUL(p, p, p);                 // P^2
            F2MUL(p, p, p);                 // P^4
            F2MUL(p, p, p);                 // P^8
            F2MUL(p, p, p);                 // P^16
            float plo, phi, rlo, rhi;
            asm("mov.b64 {%0,%1},%2;" : "=f"(plo), "=f"(phi) : "l"(p));
            asm("rcp.approx.f32 %0,%1;" : "=f"(rlo) : "f"(plo));
            asm("rcp.approx.f32 %0,%1;" : "=f"(rhi) : "f"(phi));
            ull rr; asm("mov.b64 %0,{%1,%2};" : "=l"(rr) : "f"(rlo), "f"(rhi));
            ull u; F2ADD(u, x, ax);         // x + |x|
            const ull nax = ax ^ SGNM;      // -|x|
            ull g2; F2FMA(g2, nax, rr, u);  // 2*gelu(x)
            F2FMA(acc[r], a2_s[r][j], g2, acc[r]);
        }
    }

    ((ull*)(g_G + (size_t) row0      * H))[tid] = acc[0];
    ((ull*)(g_G + (size_t)(row0 + 1) * H))[tid] = acc[1];
}

// ---------------------------------------------------------------------------
// Kernel 3: fused epilogue. 8 rows per block, 512 threads (grid 256).
//   agg = G @ W_m2 + rowsum(a)*b_m2
//   u   = slots@W_u1[:D] + agg@W_u1[D:] + b_u1 ; LayerNorm ; gelu
//   out = slots + u @ W_u2 + b_u2
// ---------------------------------------------------------------------------
__global__ __launch_bounds__(512) void epilogue_kernel(
    const float* __restrict__ slots, const float* __restrict__ adj,
    const float* __restrict__ W_m2, const float* __restrict__ b_m2,
    const float* __restrict__ W_u1, const float* __restrict__ b_u1,
    const float* __restrict__ ln_g, const float* __restrict__ ln_b,
    const float* __restrict__ W_u2, const float* __restrict__ b_u2,
    float* __restrict__ out)
{
    const int R  = 8;
    const int r0 = blockIdx.x * R;          // global row = b*N + n
    const int b  = r0 >> 8;
    const int n0 = r0 & (N - 1);
    const int tid = threadIdx.x;
    const int warp = tid >> 5, lane = tid & 31;

    __shared__ float buf_s[R][H];           // G tile, later reused as u tile
    __shared__ float s_s [R][D];
    __shared__ float agg_s[R][D];
    __shared__ float asum_s[R];
    __shared__ float mu_s[R], rstd_s[R];

    for (int idx = tid; idx < R * H; idx += 512)
        ((float*)buf_s)[idx] = g_G[r0 * H + idx];
    for (int idx = tid; idx < R * D; idx += 512)
        ((float*)s_s)[idx] = slots[r0 * D + idx];

    // adjacency row sums: warps 0..7 handle rows 0..7
    if (warp < R) {
        const float* arow = adj + ((size_t)b * N + n0 + warp) * N;
        float s = 0.f;
#pragma unroll
        for (int k = 0; k < 8; ++k) s += arow[lane + k * 32];
#pragma unroll
        for (int o = 16; o > 0; o >>= 1) s += __shfl_xor_sync(~0u, s, o);
        if (lane == 0) asum_s[warp] = s;
    }
    __syncthreads();

    // aggregated = G @ W_m2 + asum * b_m2
    // d = tid&127; 4 groups (tid>>7) x 2 rows; groups share weight addresses.
    {
        const int d  = tid & (D - 1);
        const int rb = (tid >> 7) * 2;       // rows rb, rb+1
        float acc[2];
        const float bm2 = b_m2[d];
#pragma unroll
        for (int r = 0; r < 2; ++r) acc[r] = asum_s[rb + r] * bm2;
#pragma unroll 8
        for (int hh = 0; hh < H; ++hh) {
            const float w = W_m2[hh * D + d];
#pragma unroll
            for (int r = 0; r < 2; ++r)
                acc[r] = fmaf(buf_s[rb + r][hh], w, acc[r]);
        }
        __syncthreads();                     // all reads of buf_s-as-G done
#pragma unroll
        for (int r = 0; r < 2; ++r) agg_s[rb + r][d] = acc[r];
    }
    __syncthreads();

    // u = slots@W_u1[:D] + agg@W_u1[D:] + b_u1   (overwrite buf_s)
    // h = tid&255; 2 groups (tid>>8) x 4 rows; groups share weight addresses.
    {
        const int h  = tid & 255;
        const int g  = tid >> 8;             // 0,1 -> rows 4g..4g+3
        float acc[4];
        const float bu = b_u1[h];
#pragma unroll
        for (int r = 0; r < 4; ++r) acc[r] = bu;
#pragma unroll 8
        for (int d = 0; d < D; ++d) {
            const float w1 = W_u1[d * H + h];
            const float w2 = W_u1[(D + d) * H + h];
#pragma unroll
            for (int r = 0; r < 4; ++r) {
                acc[r] = fmaf(s_s[4 * g + r][d], w1, acc[r]);
                acc[r] = fmaf(agg_s[4 * g + r][d], w2, acc[r]);
            }
        }
#pragma unroll
        for (int r = 0; r < 4; ++r) buf_s[4 * g + r][h] = acc[r];
    }
    __syncthreads();

    // LayerNorm stats: warps 0..7, one row each (two-pass)
    if (warp < R) {
        const int r = warp;
        float s = 0.f;
#pragma unroll
        for (int k = 0; k < 8; ++k) s += buf_s[r][lane + k * 32];
#pragma unroll
        for (int o = 16; o > 0; o >>= 1) s += __shfl_xor_sync(~0u, s, o);
        const float mu = s * (1.f / H);
        float ss = 0.f;
#pragma unroll
        for (int k = 0; k < 8; ++k) {
            const float v = buf_s[r][lane + k * 32] - mu;
            ss += v * v;
        }
#pragma unroll
        for (int o = 16; o > 0; o >>= 1) ss += __shfl_xor_sync(~0u, ss, o);
        if (lane == 0) {
            mu_s[r]   = mu;
            rstd_s[r] = rsqrtf(ss * (1.f / H) + 1e-5f);
        }
    }
    __syncthreads();

    // normalize + gelu (in place)
    {
        const int h = tid & 255;
        const int g = tid >> 8;
        const float gg = ln_g[h], bb = ln_b[h];
#pragma unroll
        for (int r = 0; r < 4; ++r) {
            const int rr = 4 * g + r;
            const float v = (buf_s[rr][h] - mu_s[rr]) * rstd_s[rr] * gg + bb;
            buf_s[rr][h] = gelu_exact(v);
        }
    }
    __syncthreads();

    // out = slots + u @ W_u2 + b_u2
    {
        const int d  = tid & (D - 1);
        const int rb = (tid >> 7) * 2;
        float acc[2];
        const float bu2 = b_u2[d];
#pragma unroll
        for (int r = 0; r < 2; ++r) acc[r] = bu2;
#pragma unroll 8
        for (int hh = 0; hh < H; ++hh) {
            const float w = W_u2[hh * D + d];
#pragma unroll
            for (int r = 0; r < 2; ++r)
                acc[r] = fmaf(buf_s[rb + r][hh], w, acc[r]);
        }
#pragma unroll
        for (int r = 0; r < 2; ++r)
            out[(r0 + rb + r) * D + d] = s_s[rb + r][d] + acc[r];
    }
}

// ---------------------------------------------------------------------------
extern "C" void kernel_launch(void* const* d_in, const int* in_sizes, int n_in,
                              void* d_out, int out_size)
{
    const float* slots = (const float*)d_in[0];
    const float* adj   = (const float*)d_in[1];
    const float* W_m1  = (const float*)d_in[2];
    const float* b_m1  = (const float*)d_in[3];
    const float* W_m2  = (const float*)d_in[4];
    const float* b_m2  = (const float*)d_in[5];
    const float* W_u1  = (const float*)d_in[6];
    const float* b_u1  = (const float*)d_in[7];
    const float* ln_g  = (const float*)d_in[8];
    const float* ln_b  = (const float*)d_in[9];
    const float* W_u2  = (const float*)d_in[10];
    const float* b_u2  = (const float*)d_in[11];
    float* out = (float*)d_out;

    proj_kernel<<<BN / 8, 512>>>(slots, W_m1, b_m1);
    msg_agg_kernel<<<BN / 2, 128>>>(adj);
    epilogue_kernel<<<BN / 8, 512>>>(slots, adj, W_m2, b_m2, W_u1, b_u1,
                                     ln_g, ln_b, W_u2, b_u2, out);
}